// round 2
// baseline (speedup 1.0000x reference)
#include <cuda_runtime.h>
#include <math.h>

#define T_   200
#define R_   512
#define B_   32
#define F_   128
#define BR_  4
#define C_   10
#define NCTA 128
#define VTHv 0.5f

// ---------------- device scratch (static globals; no allocation) ----------------
__device__ float  CUR [T_*R_*B_];     // currents  [t][r][b]
__device__ float  GTr [T_*R_*B_];     // gating    [t][r][b]
__device__ float  SPKH[T_*R_*B_];     // published spikes [t][r][b] (also history)
__device__ float2 PACKG[2048*256];    // per-row packed {w, col*32 as int bits}
__device__ unsigned g_bar;

// ---------------- init: reset grid barrier every launch ----------------
__global__ void init_kernel() {
    if (threadIdx.x == 0) g_bar = 0u;
}

// ---------------- phase A: currents[t][r][b] = dot(input[b][t][r][:], w_in)+b0 ----------------
__global__ void cur_kernel(const float* __restrict__ inp,
                           const float* __restrict__ w_in,
                           const float* __restrict__ b_in) {
    int lane = threadIdx.x & 31;
    int wid  = (blockIdx.x * blockDim.x + threadIdx.x) >> 5;
    int nw   = (gridDim.x * blockDim.x) >> 5;
    float4 w4 = ((const float4*)w_in)[lane];   // lane covers f = lane*4 .. +3
    float b0 = b_in[0];
    int total = B_ * T_ * R_;
    for (int rid = wid; rid < total; rid += nw) {
        const float4* src = (const float4*)(inp + (size_t)rid * F_);
        float4 v = src[lane];
        float s = v.x*w4.x + v.y*w4.y + v.z*w4.z + v.w*w4.w;
        #pragma unroll
        for (int o = 16; o > 0; o >>= 1) s += __shfl_xor_sync(0xffffffffu, s, o);
        if (lane == 0) {
            int b   = rid / (T_ * R_);
            int rem = rid - b * (T_ * R_);
            int t   = rem / R_;
            int r   = rem - t * R_;
            CUR[((size_t)t * R_ + r) * B_ + b] = s + b0;
        }
    }
}

// ---------------- gating transpose: GTr[t][r][b] = g[b][t][r] ----------------
__global__ void gt_kernel(const float* __restrict__ g) {
    __shared__ float tile[32][33];
    int t  = blockIdx.x;       // 0..199
    int rt = blockIdx.y;       // 0..15 (tiles of 32 r)
    int tx = threadIdx.x, ty = threadIdx.y;
    // read: b = ty, r = rt*32 + tx  (coalesced over tx)
    tile[ty][tx] = g[(size_t)ty * (T_ * R_) + (size_t)t * R_ + rt * 32 + tx];
    __syncthreads();
    // write: r = rt*32 + ty, b = tx (coalesced over tx)
    GTr[((size_t)t * R_ + rt * 32 + ty) * B_ + tx] = tile[tx][ty];
}

// ---------------- pack sparse rows: ascending-j compaction (warp per row) ----------------
__global__ void pack_kernel(const float* __restrict__ w_rnn,
                            const float* __restrict__ mask) {
    int lane = threadIdx.x & 31;
    int row  = (blockIdx.x * blockDim.x + threadIdx.x) >> 5;
    if (row >= 2048) return;
    int base = 0;
    for (int it = 0; it < 32; it++) {
        int j = it * 32 + lane;
        float m = mask[(size_t)row * 1024 + j];
        bool p = (m != 0.f);
        unsigned bal = __ballot_sync(0xffffffffu, p);
        int pref = __popc(bal & ((1u << lane) - 1u));
        if (p) {
            int pos = base + pref;
            if (pos < 256)
                PACKG[row * 256 + pos] =
                    make_float2(w_rnn[(size_t)row * 1024 + j] * m,
                                __int_as_float(j * B_));   // element offset col*32
        }
        base += __popc(bal);
    }
}

// ---------------- persistent sequential scan ----------------
// 128 CTAs x 256 threads. CTA c owns neurons [c*4, c*4+4) = rows [c*16, c*16+16).
// Warp wi computes proj for local rows {wi*2, wi*2+1}, lane = batch.
// Threads 0..127 do the state update: thread = (local neuron tid>>5, batch tid&31).
// CTAs 0..9 additionally run the readout for class = blockIdx, lagged one step
// so it can reuse the SMEM-resident spike slice.
__global__ void __launch_bounds__(256, 1)
snn_kernel(const float* __restrict__ b_rnn,
           const float* __restrict__ tau_m,  const float* __restrict__ tau_n,
           const float* __restrict__ w_ro,   const float* __restrict__ b_ro,
           const float* __restrict__ tau_m_ro,
           float* __restrict__ out) {
    extern __shared__ float sm[];
    float*  k_s     = sm;                       // 1024 cols x 32 batches = 32768 floats
    float2* pk_s    = (float2*)(sm + 32768);    // 16 rows x 256 = 4096 float2
    float*  proj_s  = sm + 32768 + 8192;        // 16 x 32
    float*  ro_part = proj_s + 512;             // 8 x 32
    float*  wro_s   = ro_part + 256;            // 512

    int cta  = blockIdx.x;
    int tid  = threadIdx.x;
    int lane = tid & 31;
    int wi   = tid >> 5;
    int rows_base   = cta * 16;
    int neuron_base = cta * 4;

    // weights -> SMEM (once, reused for all 200 steps)
    {
        const float2* src = PACKG + rows_base * 256;
        for (int i = tid; i < 4096; i += 256) pk_s[i] = src[i];
    }
    if (cta < C_) {
        for (int i = tid; i < R_; i += 256) wro_s[i] = w_ro[cta * R_ + i];
    }

    int lr0 = wi * 2, lr1 = lr0 + 1;
    float bias0 = b_rnn[rows_base + lr0];
    float bias1 = b_rnn[rows_base + lr1];

    // neuron state (threads 0..127)
    float d0=0.f,d1=0.f,d2=0.f,d3=0.f, mem=0.f, spk=0.f;
    float alpha=0.f, be0=0.f,be1=0.f,be2=0.f,be3=0.f;
    int ng = 0, bb = 0;
    if (tid < 128) {
        int nl = tid >> 5; bb = tid & 31; ng = neuron_base + nl;
        alpha = 1.f / (1.f + expf(-tau_m[ng]));
        be0 = 1.f / (1.f + expf(-tau_n[ng*4+0]));
        be1 = 1.f / (1.f + expf(-tau_n[ng*4+1]));
        be2 = 1.f / (1.f + expf(-tau_n[ng*4+2]));
        be3 = 1.f / (1.f + expf(-tau_n[ng*4+3]));
    }
    // readout state (CTAs 0..9, warp 0; lane = batch)
    float mem_o=0.f, spk_o=0.f, alpha_o=0.f, bro=0.f;
    if (cta < C_ && wi == 0) {
        alpha_o = 1.f / (1.f + expf(-tau_m_ro[cta]));
        bro = b_ro[cta];
    }
    __syncthreads();

    for (int t = 0; t < T_; t++) {
        // ---- load k = [currents(t) ; spikes(t-1)] into SMEM ----
        {
            const float4* csrc = (const float4*)(CUR + (size_t)t * R_ * B_);
            float4* kd = (float4*)k_s;
            #pragma unroll
            for (int i = 0; i < 16; i++) kd[tid + i * 256] = csrc[tid + i * 256];
            float4* kd2 = kd + 4096;
            if (t > 0) {
                const float4* ssrc = (const float4*)(SPKH + (size_t)(t-1) * R_ * B_);
                #pragma unroll
                for (int i = 0; i < 16; i++) kd2[tid + i * 256] = ssrc[tid + i * 256];
            } else {
                float4 z = make_float4(0.f, 0.f, 0.f, 0.f);
                #pragma unroll
                for (int i = 0; i < 16; i++) kd2[tid + i * 256] = z;
            }
        }
        __syncthreads();

        // ---- readout partial for step t-1 (spikes(t-1) are in k_s) ----
        if (cta < C_ && t > 0) {
            float racc = 0.f;
            int rb = wi * 64;
            #pragma unroll 8
            for (int r = 0; r < 64; r++)
                racc += wro_s[rb + r] * k_s[16384 + (rb + r) * 32 + lane];
            ro_part[wi * 32 + lane] = racc;
        }

        // ---- sparse proj: 2 rows per warp, 256 nz each, lane = batch ----
        {
            float a0 = bias0, a1 = bias1;
            const float2* p0 = pk_s + lr0 * 256;
            const float2* p1 = pk_s + lr1 * 256;
            #pragma unroll 8
            for (int i = 0; i < 256; i++) {
                float2 e0 = p0[i];
                float2 e1 = p1[i];
                a0 += e0.x * k_s[__float_as_int(e0.y) + lane];
                a1 += e1.x * k_s[__float_as_int(e1.y) + lane];
            }
            proj_s[lr0 * 32 + lane] = a0;
            proj_s[lr1 * 32 + lane] = a1;
        }
        __syncthreads();

        // ---- neuron state update + publish spikes ----
        if (tid < 128) {
            int nl = tid >> 5;
            float g = GTr[((size_t)t * R_ + ng) * B_ + bb];
            float p0v = proj_s[(nl*4+0) * 32 + bb];
            float p1v = proj_s[(nl*4+1) * 32 + bb];
            float p2v = proj_s[(nl*4+2) * 32 + bb];
            float p3v = proj_s[(nl*4+3) * 32 + bb];
            float dn0 = be0*d0 + (1.f-be0)*p0v;
            float dn1 = be1*d1 + (1.f-be1)*p1v;
            float dn2 = be2*d2 + (1.f-be2)*p2v;
            float dn3 = be3*d3 + (1.f-be3)*p3v;
            float lin  = dn0 + dn1 + dn2 + dn3;
            float memn = mem*alpha + (1.f-alpha)*lin - VTHv*spk;
            float spkn = (memn - VTHv) > 0.f ? 1.f : 0.f;
            float og = 1.f - g;
            d0 = g*dn0 + og*d0;  d1 = g*dn1 + og*d1;
            d2 = g*dn2 + og*d2;  d3 = g*dn3 + og*d3;
            mem = g*memn + og*mem;
            spk = g*spkn + og*spk;
            SPKH[((size_t)t * R_ + ng) * B_ + bb] = spk;
        }

        // ---- readout finalize for step t-1 ----
        if (cta < C_ && wi == 0 && t > 0) {
            float ro = bro;
            #pragma unroll
            for (int w2 = 0; w2 < 8; w2++) ro += ro_part[w2 * 32 + lane];
            mem_o = mem_o * alpha_o + (1.f - alpha_o) * ro - VTHv * spk_o;
            spk_o = (mem_o - VTHv) > 0.f ? 1.f : 0.f;
            out[lane * (C_ * T_) + cta * T_ + (t - 1)] = mem_o;   // outputs[b][c][t-1]
        }

        // ---- grid barrier (monotonic counter; 1 per step) ----
        __syncthreads();
        if (tid == 0) {
            __threadfence();
            atomicAdd(&g_bar, 1u);
            unsigned target = (unsigned)(t + 1) * (unsigned)NCTA;
            while (*((volatile unsigned*)&g_bar) < target) { __nanosleep(64); }
            __threadfence();
        }
        __syncthreads();
    }

    // ---- final readout for t = 199 (spikes(199) now globally visible) ----
    if (cta < C_) {
        float racc = 0.f;
        int rb = wi * 64;
        #pragma unroll 8
        for (int r = 0; r < 64; r++)
            racc += wro_s[rb + r] * SPKH[((size_t)(T_-1) * R_ + rb + r) * B_ + lane];
        ro_part[wi * 32 + lane] = racc;
    }
    __syncthreads();
    if (cta < C_ && wi == 0) {
        float ro = bro;
        #pragma unroll
        for (int w2 = 0; w2 < 8; w2++) ro += ro_part[w2 * 32 + lane];
        mem_o = mem_o * alpha_o + (1.f - alpha_o) * ro - VTHv * spk_o;
        out[lane * (C_ * T_) + cta * T_ + (T_ - 1)] = mem_o;
    }
}

// ---------------- spikes output transpose: out[b][r][t] = SPKH[t][r][b] ----------------
__global__ void spkout_kernel(float* __restrict__ out) {
    __shared__ float tile[32][33];
    int n  = blockIdx.x;      // neuron 0..511
    int tt = blockIdx.y;      // t tile 0..6
    int tx = threadIdx.x, ty = threadIdx.y;
    int t = tt * 32 + ty;
    if (t < T_) tile[ty][tx] = SPKH[((size_t)t * R_ + n) * B_ + tx];
    __syncthreads();
    int t2 = tt * 32 + tx;
    if (t2 < T_) {
        // spikes start after outputs (B*C*T floats)
        out[(size_t)(B_ * C_ * T_) + (size_t)ty * (R_ * T_) + (size_t)n * T_ + t2]
            = tile[tx][ty];
    }
}

// ---------------- launch ----------------
extern "C" void kernel_launch(void* const* d_in, const int* in_sizes, int n_in,
                              void* d_out, int out_size) {
    const float* inp      = (const float*)d_in[0];   // [32,200,512,128]
    const float* gat      = (const float*)d_in[1];   // [32,200,512]
    const float* w_in     = (const float*)d_in[2];   // [128]
    const float* b_in     = (const float*)d_in[3];   // [1]
    const float* w_rnn    = (const float*)d_in[4];   // [2048,1024]
    const float* b_rnn    = (const float*)d_in[5];   // [2048]
    const float* tau_m    = (const float*)d_in[6];   // [512]
    const float* tau_n    = (const float*)d_in[7];   // [512,4]
    const float* w_ro     = (const float*)d_in[8];   // [10,512]
    const float* b_ro     = (const float*)d_in[9];   // [10]
    const float* tau_m_ro = (const float*)d_in[10];  // [10]
    const float* mask     = (const float*)d_in[11];  // [2048,1024]
    float* out = (float*)d_out;

    const size_t SMEMB = (size_t)(32768 + 8192 + 512 + 256 + 512) * sizeof(float); // 168,960 B
    cudaFuncSetAttribute(snn_kernel, cudaFuncAttributeMaxDynamicSharedMemorySize, (int)SMEMB);

    init_kernel<<<1, 32>>>();
    dim3 b32(32, 32);
    gt_kernel<<<dim3(T_, R_ / 32), b32>>>(gat);
    cur_kernel<<<2048, 256>>>(inp, w_in, b_in);
    pack_kernel<<<256, 256>>>(w_rnn, mask);
    snn_kernel<<<NCTA, 256, SMEMB>>>(b_rnn, tau_m, tau_n, w_ro, b_ro, tau_m_ro, out);
    spkout_kernel<<<dim3(R_, (T_ + 31) / 32), b32>>>(out);
}

// round 3
// speedup vs baseline: 1.0211x; 1.0211x over previous
#include <cuda_runtime.h>
#include <math.h>
#include <stdint.h>

#define T_   200
#define R_   512
#define B_   32
#define F_   128
#define C_   10
#define NCTA 128
#define VTHv 0.5f
#define ROWPAD 264          // padded packed entries per row (256 nz + alignment pads)
#define STEP_ELEMS (R_*B_)  // 16384 floats per (t) slice

// ---------------- device scratch ----------------
__device__ float    CUR [T_*STEP_ELEMS];
__device__ float    GTr [T_*STEP_ELEMS];
__device__ float    SPKH[T_*STEP_ELEMS];
__device__ float    ROBUF[T_*C_*B_];
__device__ float    PW[2048*ROWPAD];
__device__ uint16_t PI[2048*ROWPAD];
__device__ int      PCUT[2048];   // end of part1 (cols<512), padded to mult of 4
__device__ int      PEND[2048];   // end of part2, padded to mult of 4
__device__ unsigned g_bar;

// ---------------- ptx helpers ----------------
__device__ __forceinline__ uint32_t smem_u32(const void* p) {
    uint32_t a;
    asm("{ .reg .u64 t; cvta.to.shared.u64 t, %1; cvt.u32.u64 %0, t; }" : "=r"(a) : "l"(p));
    return a;
}
__device__ __forceinline__ void mbar_init(uint32_t mbar, uint32_t cnt) {
    asm volatile("mbarrier.init.shared.b64 [%0], %1;" :: "r"(mbar), "r"(cnt) : "memory");
}
__device__ __forceinline__ void mbar_expect_tx(uint32_t mbar, uint32_t bytes) {
    asm volatile("mbarrier.arrive.expect_tx.shared.b64 _, [%0], %1;" :: "r"(mbar), "r"(bytes) : "memory");
}
__device__ __forceinline__ void bulk_g2s(uint32_t dst, const void* src, uint32_t bytes, uint32_t mbar) {
    asm volatile("cp.async.bulk.shared::cta.global.mbarrier::complete_tx::bytes [%0], [%1], %2, [%3];"
                 :: "r"(dst), "l"(src), "r"(bytes), "r"(mbar) : "memory");
}
__device__ __forceinline__ void mbar_wait(uint32_t mbar, uint32_t parity) {
    uint32_t done;
    asm volatile("{\n\t.reg .pred p;\n\t"
                 "mbarrier.try_wait.parity.acquire.cta.shared::cta.b64 p, [%1], %2;\n\t"
                 "selp.b32 %0, 1, 0, p;\n\t}"
                 : "=r"(done) : "r"(mbar), "r"(parity) : "memory");
    if (!done) {
        asm volatile("{\n\t.reg .pred P1;\n\t"
                     "W%=:\n\t"
                     "mbarrier.try_wait.parity.acquire.cta.shared::cta.b64 P1, [%0], %1, 0x989680;\n\t"
                     "@P1 bra.uni D%=;\n\t"
                     "bra.uni W%=;\n\t"
                     "D%=:\n\t}"
                     :: "r"(mbar), "r"(parity) : "memory");
    }
}

// ---------------- init ----------------
__global__ void init_kernel() { if (threadIdx.x == 0) g_bar = 0u; }

// ---------------- phase A: currents ----------------
__global__ void cur_kernel(const float* __restrict__ inp,
                           const float* __restrict__ w_in,
                           const float* __restrict__ b_in) {
    int lane = threadIdx.x & 31;
    int wid  = (blockIdx.x * blockDim.x + threadIdx.x) >> 5;
    int nw   = (gridDim.x * blockDim.x) >> 5;
    float4 w4 = ((const float4*)w_in)[lane];
    float b0 = b_in[0];
    int total = B_ * T_ * R_;
    for (int rid = wid; rid < total; rid += nw) {
        const float4* src = (const float4*)(inp + (size_t)rid * F_);
        float4 v = src[lane];
        float s = v.x*w4.x + v.y*w4.y + v.z*w4.z + v.w*w4.w;
        #pragma unroll
        for (int o = 16; o > 0; o >>= 1) s += __shfl_xor_sync(0xffffffffu, s, o);
        if (lane == 0) {
            int b   = rid / (T_ * R_);
            int rem = rid - b * (T_ * R_);
            int t   = rem / R_;
            int r   = rem - t * R_;
            CUR[((size_t)t * R_ + r) * B_ + b] = s + b0;
        }
    }
}

// ---------------- gating transpose ----------------
__global__ void gt_kernel(const float* __restrict__ g) {
    __shared__ float tile[32][33];
    int t  = blockIdx.x;
    int rt = blockIdx.y;
    int tx = threadIdx.x, ty = threadIdx.y;
    tile[ty][tx] = g[(size_t)ty * (T_ * R_) + (size_t)t * R_ + rt * 32 + tx];
    __syncthreads();
    GTr[((size_t)t * R_ + rt * 32 + ty) * B_ + tx] = tile[tx][ty];
}

// ---------------- pack: split per row at col 512, pad to multiples of 4 ----------------
__global__ void pack_kernel(const float* __restrict__ w_rnn,
                            const float* __restrict__ mask) {
    int lane = threadIdx.x & 31;
    int row  = (blockIdx.x * blockDim.x + threadIdx.x) >> 5;
    if (row >= 2048) return;
    const float* mrow = mask  + (size_t)row * 1024;
    const float* wrow = w_rnn + (size_t)row * 1024;
    // pass 1: count nz with col<512
    int cut = 0;
    for (int it = 0; it < 16; it++) {
        float m = mrow[it * 32 + lane];
        cut += __popc(__ballot_sync(0xffffffffu, m != 0.f));
    }
    int cut4 = (cut + 3) & ~3;
    // zero-fill padded arrays
    for (int i = lane; i < ROWPAD; i += 32) {
        PW[(size_t)row * ROWPAD + i] = 0.f;
        PI[(size_t)row * ROWPAD + i] = 0;
    }
    __syncwarp();
    // pass 2: compaction (chunks of 32 never straddle col 512)
    int base1 = 0, base2 = cut4;
    for (int it = 0; it < 32; it++) {
        int j = it * 32 + lane;
        float m = mrow[j];
        bool p = (m != 0.f);
        unsigned bal = __ballot_sync(0xffffffffu, p);
        int pref = __popc(bal & ((1u << lane) - 1u));
        bool first_half = (j < 512);
        if (p) {
            int pos = (first_half ? base1 : base2) + pref;
            PW[(size_t)row * ROWPAD + pos] = wrow[j] * m;
            PI[(size_t)row * ROWPAD + pos] = (uint16_t)(first_half ? j : j - 512);
        }
        int cnt = __popc(bal);
        if (first_half) base1 += cnt; else base2 += cnt;
    }
    if (lane == 0) {
        PCUT[row] = cut4;
        int n2 = 256 - cut;
        PEND[row] = cut4 + ((n2 + 3) & ~3);
    }
}

// ---------------- persistent scan ----------------
// SMEM layout (bytes):
//   cur0   @0        65536
//   cur1   @65536    65536
//   spk    @131072   65536
//   w_s    @196608   16896  (16 rows x 264 float)
//   i_s    @213504    8448  (16 rows x 264 u16)
//   proj   @221952    2048  (16 x 32 float)
//   cuts   @224000     128  (16 x {cut4, end4})
//   mbars  @224128      24
#define SM_CUR0 0
#define SM_CUR1 65536
#define SM_SPK  131072
#define SM_W    196608
#define SM_I    213504
#define SM_PROJ 221952
#define SM_CUTS 224000
#define SM_MBAR 224128
#define SM_TOTAL 224160

__global__ void __launch_bounds__(256, 1)
snn_kernel(const float* __restrict__ b_rnn,
           const float* __restrict__ tau_m, const float* __restrict__ tau_n) {
    extern __shared__ char sm[];
    float*    cur_s[2] = { (float*)(sm + SM_CUR0), (float*)(sm + SM_CUR1) };
    float*    spk_s    = (float*)(sm + SM_SPK);
    float*    w_s      = (float*)(sm + SM_W);
    uint16_t* i_s      = (uint16_t*)(sm + SM_I);
    float*    proj_s   = (float*)(sm + SM_PROJ);
    int*      cuts_s   = (int*)(sm + SM_CUTS);

    uint32_t smb       = smem_u32(sm);
    uint32_t mb_cur0   = smb + SM_MBAR;
    uint32_t mb_cur1   = smb + SM_MBAR + 8;
    uint32_t mb_spk    = smb + SM_MBAR + 16;
    uint32_t sm_cur_u[2] = { smb + SM_CUR0, smb + SM_CUR1 };

    int cta  = blockIdx.x;
    int tid  = threadIdx.x;
    int lane = tid & 31;
    int wi   = tid >> 5;
    int rows_base   = cta * 16;
    int neuron_base = cta * 4;

    // load packed weights/indices (constant across steps)
    {
        const float* src = PW + (size_t)rows_base * ROWPAD;
        for (int i = tid; i < 16 * ROWPAD; i += 256) w_s[i] = src[i];
        const uint16_t* isrc = PI + (size_t)rows_base * ROWPAD;
        for (int i = tid; i < 16 * ROWPAD; i += 256) i_s[i] = isrc[i];
        if (tid < 16) {
            cuts_s[tid * 2 + 0] = PCUT[rows_base + tid];
            cuts_s[tid * 2 + 1] = PEND[rows_base + tid];
        }
    }
    // zero spike buffer for t=0
    {
        float4 z = make_float4(0.f, 0.f, 0.f, 0.f);
        float4* sd = (float4*)spk_s;
        #pragma unroll
        for (int i = 0; i < 16; i++) sd[tid + i * 256] = z;
    }
    if (tid == 0) {
        mbar_init(mb_cur0, 1);
        mbar_init(mb_cur1, 1);
        mbar_init(mb_spk, 1);
    }
    asm volatile("fence.proxy.async.shared::cta;" ::: "memory");
    __syncthreads();
    if (tid == 0) {
        mbar_expect_tx(mb_cur0, STEP_ELEMS * 4);
        bulk_g2s(sm_cur_u[0], CUR, STEP_ELEMS * 4, mb_cur0);
    }

    int lr0 = wi * 2, lr1 = lr0 + 1;
    float bias0 = b_rnn[rows_base + lr0];
    float bias1 = b_rnn[rows_base + lr1];
    int cut0 = cuts_s[lr0 * 2], end0 = cuts_s[lr0 * 2 + 1];
    int cut1 = cuts_s[lr1 * 2], end1 = cuts_s[lr1 * 2 + 1];

    // neuron state (threads 0..127): thread = (local neuron tid>>5, batch tid&31)
    float d0=0.f,d1=0.f,d2=0.f,d3=0.f, mem=0.f, spk=0.f;
    float alpha=0.f, be0=0.f,be1=0.f,be2=0.f,be3=0.f;
    int ng = 0, bb = 0;
    if (tid < 128) {
        int nl = tid >> 5; bb = tid & 31; ng = neuron_base + nl;
        alpha = 1.f / (1.f + expf(-tau_m[ng]));
        be0 = 1.f / (1.f + expf(-tau_n[ng*4+0]));
        be1 = 1.f / (1.f + expf(-tau_n[ng*4+1]));
        be2 = 1.f / (1.f + expf(-tau_n[ng*4+2]));
        be3 = 1.f / (1.f + expf(-tau_n[ng*4+3]));
    }

    int ph_cur0 = 0, ph_cur1 = 0, ph_spk = 0;

    for (int t = 0; t < T_; t++) {
        // issue async copies: spikes(t-1) and currents(t+1)
        if (tid == 0) {
            if (t > 0) {
                mbar_expect_tx(mb_spk, STEP_ELEMS * 4);
                bulk_g2s(smb + SM_SPK, SPKH + (size_t)(t-1) * STEP_ELEMS, STEP_ELEMS * 4, mb_spk);
            }
            if (t + 1 < T_) {
                uint32_t mb = ((t+1) & 1) ? mb_cur1 : mb_cur0;
                mbar_expect_tx(mb, STEP_ELEMS * 4);
                bulk_g2s(sm_cur_u[(t+1) & 1], CUR + (size_t)(t+1) * STEP_ELEMS, STEP_ELEMS * 4, mb);
            }
        }
        // prefetch gate value (needed only in the update phase)
        float g = 0.f;
        if (tid < 128) g = GTr[((size_t)t * R_ + ng) * B_ + bb];

        // wait for currents(t)
        if ((t & 1) == 0) { mbar_wait(mb_cur0, ph_cur0); ph_cur0 ^= 1; }
        else              { mbar_wait(mb_cur1, ph_cur1); ph_cur1 ^= 1; }
        const float* kc = cur_s[t & 1] + lane;

        // part 1: currents-indexed nz (spike copy in flight underneath)
        float a0a = bias0, a0b = 0.f, a1a = bias1, a1b = 0.f;
        {
            const float* wr = w_s + lr0 * ROWPAD;
            const uint16_t* ir = i_s + lr0 * ROWPAD;
            #pragma unroll 2
            for (int i = 0; i < cut0; i += 4) {
                float4 w4 = *(const float4*)(wr + i);
                uint2 ip  = *(const uint2*)(ir + i);
                a0a += w4.x * kc[(ip.x & 0xFFFFu) << 5];
                a0b += w4.y * kc[(ip.x >> 16) << 5];
                a0a += w4.z * kc[(ip.y & 0xFFFFu) << 5];
                a0b += w4.w * kc[(ip.y >> 16) << 5];
            }
            wr = w_s + lr1 * ROWPAD;
            ir = i_s + lr1 * ROWPAD;
            #pragma unroll 2
            for (int i = 0; i < cut1; i += 4) {
                float4 w4 = *(const float4*)(wr + i);
                uint2 ip  = *(const uint2*)(ir + i);
                a1a += w4.x * kc[(ip.x & 0xFFFFu) << 5];
                a1b += w4.y * kc[(ip.x >> 16) << 5];
                a1a += w4.z * kc[(ip.y & 0xFFFFu) << 5];
                a1b += w4.w * kc[(ip.y >> 16) << 5];
            }
        }

        // wait for spikes(t-1)
        if (t > 0) { mbar_wait(mb_spk, ph_spk); ph_spk ^= 1; }
        const float* ks = spk_s + lane;

        // part 2: spike-indexed nz
        {
            const float* wr = w_s + lr0 * ROWPAD;
            const uint16_t* ir = i_s + lr0 * ROWPAD;
            #pragma unroll 2
            for (int i = cut0; i < end0; i += 4) {
                float4 w4 = *(const float4*)(wr + i);
                uint2 ip  = *(const uint2*)(ir + i);
                a0a += w4.x * ks[(ip.x & 0xFFFFu) << 5];
                a0b += w4.y * ks[(ip.x >> 16) << 5];
                a0a += w4.z * ks[(ip.y & 0xFFFFu) << 5];
                a0b += w4.w * ks[(ip.y >> 16) << 5];
            }
            wr = w_s + lr1 * ROWPAD;
            ir = i_s + lr1 * ROWPAD;
            #pragma unroll 2
            for (int i = cut1; i < end1; i += 4) {
                float4 w4 = *(const float4*)(wr + i);
                uint2 ip  = *(const uint2*)(ir + i);
                a1a += w4.x * ks[(ip.x & 0xFFFFu) << 5];
                a1b += w4.y * ks[(ip.x >> 16) << 5];
                a1a += w4.z * ks[(ip.y & 0xFFFFu) << 5];
                a1b += w4.w * ks[(ip.y >> 16) << 5];
            }
        }
        proj_s[lr0 * 32 + lane] = a0a + a0b;
        proj_s[lr1 * 32 + lane] = a1a + a1b;
        __syncthreads();

        // state update + publish spikes
        if (tid < 128) {
            int nl = tid >> 5;
            float p0v = proj_s[(nl*4+0) * 32 + bb];
            float p1v = proj_s[(nl*4+1) * 32 + bb];
            float p2v = proj_s[(nl*4+2) * 32 + bb];
            float p3v = proj_s[(nl*4+3) * 32 + bb];
            float dn0 = be0*d0 + (1.f-be0)*p0v;
            float dn1 = be1*d1 + (1.f-be1)*p1v;
            float dn2 = be2*d2 + (1.f-be2)*p2v;
            float dn3 = be3*d3 + (1.f-be3)*p3v;
            float lin  = dn0 + dn1 + dn2 + dn3;
            float memn = mem*alpha + (1.f-alpha)*lin - VTHv*spk;
            float spkn = (memn - VTHv) > 0.f ? 1.f : 0.f;
            float og = 1.f - g;
            d0 = g*dn0 + og*d0;  d1 = g*dn1 + og*d1;
            d2 = g*dn2 + og*d2;  d3 = g*dn3 + og*d3;
            mem = g*memn + og*mem;
            spk = g*spkn + og*spk;
            SPKH[((size_t)t * R_ + ng) * B_ + bb] = spk;
        }
        __syncthreads();

        // grid barrier (skip after last step)
        if (t + 1 < T_) {
            if (tid == 0) {
                __threadfence();
                atomicAdd(&g_bar, 1u);
                unsigned target = (unsigned)(t + 1) * (unsigned)NCTA;
                while (*((volatile unsigned*)&g_bar) < target) { __nanosleep(32); }
                __threadfence();
            }
            __syncthreads();
        }
    }
}

// ---------------- readout GEMM (parallel over t) ----------------
__global__ void ro_gemm(const float* __restrict__ w_ro, const float* __restrict__ b_ro) {
    int t = blockIdx.x;
    int c = threadIdx.x >> 5;
    int lane = threadIdx.x & 31;
    const float* sp = SPKH + (size_t)t * STEP_ELEMS + lane;
    const float* wr = w_ro + c * R_;
    float acc0 = b_ro[c], acc1 = 0.f;
    #pragma unroll 8
    for (int r = 0; r < R_; r += 2) {
        acc0 += wr[r]   * sp[(r)   * 32];
        acc1 += wr[r+1] * sp[(r+1) * 32];
    }
    ROBUF[(size_t)t * (C_*B_) + c * 32 + lane] = acc0 + acc1;
}

// ---------------- readout LIF scan (sequential over t; 320 threads) ----------------
__global__ void ro_scan(const float* __restrict__ tau_m_ro, float* __restrict__ out) {
    int tid = threadIdx.x;
    if (tid >= C_ * B_) return;
    int c = tid >> 5, b = tid & 31;
    float ao = 1.f / (1.f + expf(-tau_m_ro[c]));
    float mem_o = 0.f, spk_o = 0.f;
    for (int t = 0; t < T_; t++) {
        float v = ROBUF[(size_t)t * (C_*B_) + c * 32 + b];
        mem_o = mem_o * ao + (1.f - ao) * v - VTHv * spk_o;
        spk_o = (mem_o - VTHv) > 0.f ? 1.f : 0.f;
        out[(size_t)b * (C_*T_) + c * T_ + t] = mem_o;
    }
}

// ---------------- spikes output transpose ----------------
__global__ void spkout_kernel(float* __restrict__ out) {
    __shared__ float tile[32][33];
    int n  = blockIdx.x;
    int tt = blockIdx.y;
    int tx = threadIdx.x, ty = threadIdx.y;
    int t = tt * 32 + ty;
    if (t < T_) tile[ty][tx] = SPKH[((size_t)t * R_ + n) * B_ + tx];
    __syncthreads();
    int t2 = tt * 32 + tx;
    if (t2 < T_) {
        out[(size_t)(B_ * C_ * T_) + (size_t)ty * (R_ * T_) + (size_t)n * T_ + t2]
            = tile[tx][ty];
    }
}

// ---------------- launch ----------------
extern "C" void kernel_launch(void* const* d_in, const int* in_sizes, int n_in,
                              void* d_out, int out_size) {
    const float* inp      = (const float*)d_in[0];
    const float* gat      = (const float*)d_in[1];
    const float* w_in     = (const float*)d_in[2];
    const float* b_in     = (const float*)d_in[3];
    const float* w_rnn    = (const float*)d_in[4];
    const float* b_rnn    = (const float*)d_in[5];
    const float* tau_m    = (const float*)d_in[6];
    const float* tau_n    = (const float*)d_in[7];
    const float* w_ro     = (const float*)d_in[8];
    const float* b_ro     = (const float*)d_in[9];
    const float* tau_m_ro = (const float*)d_in[10];
    const float* mask     = (const float*)d_in[11];
    float* out = (float*)d_out;

    cudaFuncSetAttribute(snn_kernel, cudaFuncAttributeMaxDynamicSharedMemorySize, SM_TOTAL);

    init_kernel<<<1, 32>>>();
    dim3 b32(32, 32);
    gt_kernel<<<dim3(T_, R_ / 32), b32>>>(gat);
    cur_kernel<<<2048, 256>>>(inp, w_in, b_in);
    pack_kernel<<<256, 256>>>(w_rnn, mask);
    snn_kernel<<<NCTA, 256, SM_TOTAL>>>(b_rnn, tau_m, tau_n);
    ro_gemm<<<T_, C_ * 32>>>(w_ro, b_ro);
    ro_scan<<<1, C_ * 32>>>(tau_m_ro, out);
    spkout_kernel<<<dim3(R_, (T_ + 31) / 32), b32>>>(out);
}

// round 5
// speedup vs baseline: 1.5372x; 1.5055x over previous
#include <cuda_runtime.h>
#include <math.h>
#include <stdint.h>

#define T_   200
#define R_   512
#define B_   32
#define F_   128
#define C_   10
#define NCTA 128
#define VTHv 0.5f
#define ROWPAD 264          // packed entries per row, parts padded to multiples of 8
#define STEP_ELEMS (R_*B_)  // 16384 floats per t slice

// ---------------- device scratch ----------------
__device__ float    CUR [T_*STEP_ELEMS];
__device__ float    GTr [T_*STEP_ELEMS];
__device__ float    SPKH[T_*STEP_ELEMS];
__device__ float    ROBUF[T_*C_*B_];
__device__ float2   PKP[2048*ROWPAD];   // {w, byte_off_as_float_bits}
__device__ int      PCUT[2048];         // end of part1 (mult of 8)
__device__ int      PEND[2048];         // end of part2 (mult of 8)
__device__ unsigned g_bar;

// ---------------- ptx helpers ----------------
__device__ __forceinline__ uint32_t smem_u32(const void* p) {
    uint32_t a;
    asm("{ .reg .u64 t; cvta.to.shared.u64 t, %1; cvt.u32.u64 %0, t; }" : "=r"(a) : "l"(p));
    return a;
}
__device__ __forceinline__ void mbar_init(uint32_t mbar, uint32_t cnt) {
    asm volatile("mbarrier.init.shared.b64 [%0], %1;" :: "r"(mbar), "r"(cnt) : "memory");
}
__device__ __forceinline__ void mbar_expect_tx(uint32_t mbar, uint32_t bytes) {
    asm volatile("mbarrier.arrive.expect_tx.shared.b64 _, [%0], %1;" :: "r"(mbar), "r"(bytes) : "memory");
}
__device__ __forceinline__ void bulk_g2s(uint32_t dst, const void* src, uint32_t bytes, uint32_t mbar) {
    asm volatile("cp.async.bulk.shared::cta.global.mbarrier::complete_tx::bytes [%0], [%1], %2, [%3];"
                 :: "r"(dst), "l"(src), "r"(bytes), "r"(mbar) : "memory");
}
__device__ __forceinline__ void mbar_wait(uint32_t mbar, uint32_t parity) {
    uint32_t done;
    asm volatile("{\n\t.reg .pred p;\n\t"
                 "mbarrier.try_wait.parity.acquire.cta.shared::cta.b64 p, [%1], %2;\n\t"
                 "selp.b32 %0, 1, 0, p;\n\t}"
                 : "=r"(done) : "r"(mbar), "r"(parity) : "memory");
    if (!done) {
        asm volatile("{\n\t.reg .pred P1;\n\t"
                     "W%=:\n\t"
                     "mbarrier.try_wait.parity.acquire.cta.shared::cta.b64 P1, [%0], %1, 0x989680;\n\t"
                     "@P1 bra.uni D%=;\n\t"
                     "bra.uni W%=;\n\t"
                     "D%=:\n\t}"
                     :: "r"(mbar), "r"(parity) : "memory");
    }
}
__device__ __forceinline__ float4 lds128(uint32_t addr) {
    float4 v;
    asm volatile("ld.shared.v4.f32 {%0,%1,%2,%3}, [%4];"
                 : "=f"(v.x), "=f"(v.y), "=f"(v.z), "=f"(v.w) : "r"(addr));
    return v;
}

// ---------------- init ----------------
__global__ void init_kernel() { if (threadIdx.x == 0) g_bar = 0u; }

// ---------------- phase A: currents ----------------
__global__ void cur_kernel(const float* __restrict__ inp,
                           const float* __restrict__ w_in,
                           const float* __restrict__ b_in) {
    int lane = threadIdx.x & 31;
    int wid  = (blockIdx.x * blockDim.x + threadIdx.x) >> 5;
    int nw   = (gridDim.x * blockDim.x) >> 5;
    float4 w4 = ((const float4*)w_in)[lane];
    float b0 = b_in[0];
    int total = B_ * T_ * R_;
    for (int rid = wid; rid < total; rid += nw) {
        const float4* src = (const float4*)(inp + (size_t)rid * F_);
        float4 v = src[lane];
        float s = v.x*w4.x + v.y*w4.y + v.z*w4.z + v.w*w4.w;
        #pragma unroll
        for (int o = 16; o > 0; o >>= 1) s += __shfl_xor_sync(0xffffffffu, s, o);
        if (lane == 0) {
            int b   = rid / (T_ * R_);
            int rem = rid - b * (T_ * R_);
            int t   = rem / R_;
            int r   = rem - t * R_;
            CUR[((size_t)t * R_ + r) * B_ + b] = s + b0;
        }
    }
}

// ---------------- gating transpose ----------------
__global__ void gt_kernel(const float* __restrict__ g) {
    __shared__ float tile[32][33];
    int t  = blockIdx.x;
    int rt = blockIdx.y;
    int tx = threadIdx.x, ty = threadIdx.y;
    tile[ty][tx] = g[(size_t)ty * (T_ * R_) + (size_t)t * R_ + rt * 32 + tx];
    __syncthreads();
    GTr[((size_t)t * R_ + rt * 32 + ty) * B_ + tx] = tile[tx][ty];
}

// ---------------- pack: {w, byte_off} pairs, split at col 512, pad to mult of 8 ----------------
__global__ void pack_kernel(const float* __restrict__ w_rnn,
                            const float* __restrict__ mask) {
    int lane = threadIdx.x & 31;
    int row  = (blockIdx.x * blockDim.x + threadIdx.x) >> 5;
    if (row >= 2048) return;
    const float* mrow = mask  + (size_t)row * 1024;
    const float* wrow = w_rnn + (size_t)row * 1024;
    // pass 1: count nz with col<512
    int cut = 0;
    for (int it = 0; it < 16; it++) {
        float m = mrow[it * 32 + lane];
        cut += __popc(__ballot_sync(0xffffffffu, m != 0.f));
    }
    int cut8 = (cut + 7) & ~7;
    // zero-fill padded array
    for (int i = lane; i < ROWPAD; i += 32)
        PKP[(size_t)row * ROWPAD + i] = make_float2(0.f, __int_as_float(0));
    __syncwarp();
    // pass 2: compaction (chunks of 32 never straddle col 512)
    int base1 = 0, base2 = cut8;
    for (int it = 0; it < 32; it++) {
        int j = it * 32 + lane;
        float m = mrow[j];
        bool p = (m != 0.f);
        unsigned bal = __ballot_sync(0xffffffffu, p);
        int pref = __popc(bal & ((1u << lane) - 1u));
        bool first_half = (j < 512);
        if (p) {
            int pos = (first_half ? base1 : base2) + pref;
            int off = (first_half ? j : j - 512) * (B_ * 4);   // byte offset
            PKP[(size_t)row * ROWPAD + pos] = make_float2(wrow[j] * m, __int_as_float(off));
        }
        int cnt = __popc(bal);
        if (first_half) base1 += cnt; else base2 += cnt;
    }
    if (lane == 0) {
        PCUT[row] = cut8;
        int n2 = 256 - cut;
        PEND[row] = cut8 + ((n2 + 7) & ~7);
    }
}

// ---------------- persistent scan ----------------
// SMEM layout (bytes):
//   cur    @0        65536
//   spk    @65536    65536
//   pairs  @131072   33792  (16 rows x 264 float2)
//   proj   @164864    2048  (16 x 32 float)
//   cuts   @166912     128
//   mbar   @167040      16
#define SM_CUR  0
#define SM_SPK  65536
#define SM_PAIR 131072
#define SM_PROJ 164864
#define SM_CUTS 166912
#define SM_MBAR 167040
#define SM_TOTAL 167072

__global__ void __launch_bounds__(512, 1)
snn_kernel(const float* __restrict__ b_rnn,
           const float* __restrict__ tau_m, const float* __restrict__ tau_n) {
    extern __shared__ char sm[];
    float2* pair_s = (float2*)(sm + SM_PAIR);
    float*  proj_s = (float*)(sm + SM_PROJ);
    int*    cuts_s = (int*)(sm + SM_CUTS);

    uint32_t smb    = smem_u32(sm);
    uint32_t mb_cur = smb + SM_MBAR;
    uint32_t mb_spk = smb + SM_MBAR + 8;

    int cta  = blockIdx.x;
    int tid  = threadIdx.x;
    int lane = tid & 31;
    int wi   = tid >> 5;              // 0..15 = local row
    int rows_base   = cta * 16;
    int neuron_base = cta * 4;

    // load packed pairs (constant across steps)
    {
        const float2* src = PKP + (size_t)rows_base * ROWPAD;
        for (int i = tid; i < 16 * ROWPAD; i += 512) pair_s[i] = src[i];
        if (tid < 16) {
            cuts_s[tid * 2 + 0] = PCUT[rows_base + tid];
            cuts_s[tid * 2 + 1] = PEND[rows_base + tid];
        }
    }
    // zero spike buffer (t=0 sees spikes(-1)=0)
    {
        float4 z = make_float4(0.f, 0.f, 0.f, 0.f);
        float4* sd = (float4*)(sm + SM_SPK);
        #pragma unroll
        for (int i = 0; i < 8; i++) sd[tid + i * 512] = z;
    }
    if (tid == 0) { mbar_init(mb_cur, 1); mbar_init(mb_spk, 1); }
    asm volatile("fence.proxy.async.shared::cta;" ::: "memory");
    __syncthreads();
    if (tid == 0) {
        mbar_expect_tx(mb_cur, STEP_ELEMS * 4);
        bulk_g2s(smb + SM_CUR, CUR, STEP_ELEMS * 4, mb_cur);
    }

    float bias = b_rnn[rows_base + wi];
    int cut8 = cuts_s[wi * 2], end8 = cuts_s[wi * 2 + 1];

    int sub = lane >> 3;              // 0..3 (entry pair group)
    int q   = lane & 7;               // batch quad
    uint32_t bc = smb + SM_CUR + q * 16;
    uint32_t bs = smb + SM_SPK + q * 16;
    const float2* prow = pair_s + wi * ROWPAD + 2 * sub;

    // neuron state (threads 0..127): thread = (local neuron tid>>5, batch tid&31)
    float d0=0.f,d1=0.f,d2=0.f,d3=0.f, mem=0.f, spk=0.f;
    float alpha=0.f, be0=0.f,be1=0.f,be2=0.f,be3=0.f;
    int ng = 0, bb = 0;
    if (tid < 128) {
        int nl = tid >> 5; bb = tid & 31; ng = neuron_base + nl;
        alpha = 1.f / (1.f + expf(-tau_m[ng]));
        be0 = 1.f / (1.f + expf(-tau_n[ng*4+0]));
        be1 = 1.f / (1.f + expf(-tau_n[ng*4+1]));
        be2 = 1.f / (1.f + expf(-tau_n[ng*4+2]));
        be3 = 1.f / (1.f + expf(-tau_n[ng*4+3]));
    }

    int ph_cur = 0, ph_spk = 0;

    for (int t = 0; t < T_; t++) {
        // issue spike(t-1) copy (spk buffer free: consumed in part2 of t-1, barrier passed)
        if (tid == 0 && t > 0) {
            mbar_expect_tx(mb_spk, STEP_ELEMS * 4);
            bulk_g2s(smb + SM_SPK, SPKH + (size_t)(t-1) * STEP_ELEMS, STEP_ELEMS * 4, mb_spk);
        }
        // prefetch gate value
        float g = 0.f;
        if (tid < 128) g = GTr[((size_t)t * R_ + ng) * B_ + bb];

        // wait for currents(t)
        mbar_wait(mb_cur, ph_cur); ph_cur ^= 1;

        // part 1: currents-indexed entries (spike copy in flight underneath)
        float4 acc = make_float4(0.f, 0.f, 0.f, 0.f);
        {
            #pragma unroll 2
            for (int i = 0; i < cut8; i += 8) {
                float4 pp = *(const float4*)(prow + i);       // 2 pairs
                uint32_t aA = bc + (uint32_t)__float_as_int(pp.y);
                uint32_t aB = bc + (uint32_t)__float_as_int(pp.w);
                float4 va = lds128(aA);
                float4 vb = lds128(aB);
                acc.x += pp.x*va.x; acc.y += pp.x*va.y; acc.z += pp.x*va.z; acc.w += pp.x*va.w;
                acc.x += pp.z*vb.x; acc.y += pp.z*vb.y; acc.z += pp.z*vb.z; acc.w += pp.z*vb.w;
            }
        }
        __syncthreads();   // all warps done reading cur buffer

        // prefetch currents(t+1) into the (now free) cur buffer
        if (tid == 0 && t + 1 < T_) {
            mbar_expect_tx(mb_cur, STEP_ELEMS * 4);
            bulk_g2s(smb + SM_CUR, CUR + (size_t)(t+1) * STEP_ELEMS, STEP_ELEMS * 4, mb_cur);
        }

        // wait for spikes(t-1)
        if (t > 0) { mbar_wait(mb_spk, ph_spk); ph_spk ^= 1; }

        // part 2: spike-indexed entries
        {
            #pragma unroll 2
            for (int i = cut8; i < end8; i += 8) {
                float4 pp = *(const float4*)(prow + i);
                uint32_t aA = bs + (uint32_t)__float_as_int(pp.y);
                uint32_t aB = bs + (uint32_t)__float_as_int(pp.w);
                float4 va = lds128(aA);
                float4 vb = lds128(aB);
                acc.x += pp.x*va.x; acc.y += pp.x*va.y; acc.z += pp.x*va.z; acc.w += pp.x*va.w;
                acc.x += pp.z*vb.x; acc.y += pp.z*vb.y; acc.z += pp.z*vb.z; acc.w += pp.z*vb.w;
            }
        }
        // reduce over the 4 entry-groups (lanes with equal q)
        acc.x += __shfl_xor_sync(0xffffffffu, acc.x, 8);
        acc.y += __shfl_xor_sync(0xffffffffu, acc.y, 8);
        acc.z += __shfl_xor_sync(0xffffffffu, acc.z, 8);
        acc.w += __shfl_xor_sync(0xffffffffu, acc.w, 8);
        acc.x += __shfl_xor_sync(0xffffffffu, acc.x, 16);
        acc.y += __shfl_xor_sync(0xffffffffu, acc.y, 16);
        acc.z += __shfl_xor_sync(0xffffffffu, acc.z, 16);
        acc.w += __shfl_xor_sync(0xffffffffu, acc.w, 16);
        if (lane < 8) {
            float4 o = make_float4(acc.x + bias, acc.y + bias, acc.z + bias, acc.w + bias);
            *(float4*)(proj_s + wi * 32 + lane * 4) = o;
        }
        __syncthreads();   // proj ready

        // state update + publish spikes
        if (tid < 128) {
            int nl = tid >> 5;
            float p0v = proj_s[(nl*4+0) * 32 + bb];
            float p1v = proj_s[(nl*4+1) * 32 + bb];
            float p2v = proj_s[(nl*4+2) * 32 + bb];
            float p3v = proj_s[(nl*4+3) * 32 + bb];
            float dn0 = be0*d0 + (1.f-be0)*p0v;
            float dn1 = be1*d1 + (1.f-be1)*p1v;
            float dn2 = be2*d2 + (1.f-be2)*p2v;
            float dn3 = be3*d3 + (1.f-be3)*p3v;
            float lin  = dn0 + dn1 + dn2 + dn3;
            float memn = mem*alpha + (1.f-alpha)*lin - VTHv*spk;
            float spkn = (memn - VTHv) > 0.f ? 1.f : 0.f;
            float og = 1.f - g;
            d0 = g*dn0 + og*d0;  d1 = g*dn1 + og*d1;
            d2 = g*dn2 + og*d2;  d3 = g*dn3 + og*d3;
            mem = g*memn + og*mem;
            spk = g*spkn + og*spk;
            SPKH[((size_t)t * R_ + ng) * B_ + bb] = spk;
        }
        __syncthreads();

        // grid barrier (skip after last step)
        if (t + 1 < T_) {
            if (tid == 0) {
                __threadfence();
                atomicAdd(&g_bar, 1u);
                unsigned target = (unsigned)(t + 1) * (unsigned)NCTA;
                while (*((volatile unsigned*)&g_bar) < target) { __nanosleep(32); }
                __threadfence();
            }
            __syncthreads();
        }
    }
}

// ---------------- readout GEMM (parallel over t) ----------------
__global__ void ro_gemm(const float* __restrict__ w_ro, const float* __restrict__ b_ro) {
    int t = blockIdx.x;
    int c = threadIdx.x >> 5;
    int lane = threadIdx.x & 31;
    const float* sp = SPKH + (size_t)t * STEP_ELEMS + lane;
    const float* wr = w_ro + c * R_;
    float acc0 = b_ro[c], acc1 = 0.f;
    #pragma unroll 8
    for (int r = 0; r < R_; r += 2) {
        acc0 += wr[r]   * sp[(r)   * 32];
        acc1 += wr[r+1] * sp[(r+1) * 32];
    }
    ROBUF[(size_t)t * (C_*B_) + c * 32 + lane] = acc0 + acc1;
}

// ---------------- readout LIF scan ----------------
__global__ void ro_scan(const float* __restrict__ tau_m_ro, float* __restrict__ out) {
    int tid = threadIdx.x;
    if (tid >= C_ * B_) return;
    int c = tid >> 5, b = tid & 31;
    float ao = 1.f / (1.f + expf(-tau_m_ro[c]));
    float mem_o = 0.f, spk_o = 0.f;
    for (int t = 0; t < T_; t++) {
        float v = ROBUF[(size_t)t * (C_*B_) + c * 32 + b];
        mem_o = mem_o * ao + (1.f - ao) * v - VTHv * spk_o;
        spk_o = (mem_o - VTHv) > 0.f ? 1.f : 0.f;
        out[(size_t)b * (C_*T_) + c * T_ + t] = mem_o;
    }
}

// ---------------- spikes output transpose ----------------
__global__ void spkout_kernel(float* __restrict__ out) {
    __shared__ float tile[32][33];
    int n  = blockIdx.x;
    int tt = blockIdx.y;
    int tx = threadIdx.x, ty = threadIdx.y;
    int t = tt * 32 + ty;
    if (t < T_) tile[ty][tx] = SPKH[((size_t)t * R_ + n) * B_ + tx];
    __syncthreads();
    int t2 = tt * 32 + tx;
    if (t2 < T_) {
        out[(size_t)(B_ * C_ * T_) + (size_t)ty * (R_ * T_) + (size_t)n * T_ + t2]
            = tile[tx][ty];
    }
}

// ---------------- launch ----------------
extern "C" void kernel_launch(void* const* d_in, const int* in_sizes, int n_in,
                              void* d_out, int out_size) {
    const float* inp      = (const float*)d_in[0];
    const float* gat      = (const float*)d_in[1];
    const float* w_in     = (const float*)d_in[2];
    const float* b_in     = (const float*)d_in[3];
    const float* w_rnn    = (const float*)d_in[4];
    const float* b_rnn    = (const float*)d_in[5];
    const float* tau_m    = (const float*)d_in[6];
    const float* tau_n    = (const float*)d_in[7];
    const float* w_ro     = (const float*)d_in[8];
    const float* b_ro     = (const float*)d_in[9];
    const float* tau_m_ro = (const float*)d_in[10];
    const float* mask     = (const float*)d_in[11];
    float* out = (float*)d_out;

    cudaFuncSetAttribute(snn_kernel, cudaFuncAttributeMaxDynamicSharedMemorySize, SM_TOTAL);

    init_kernel<<<1, 32>>>();
    dim3 b32(32, 32);
    gt_kernel<<<dim3(T_, R_ / 32), b32>>>(gat);
    cur_kernel<<<2048, 256>>>(inp, w_in, b_in);
    pack_kernel<<<256, 256>>>(w_rnn, mask);
    snn_kernel<<<NCTA, 512, SM_TOTAL>>>(b_rnn, tau_m, tau_n);
    ro_gemm<<<T_, C_ * 32>>>(w_ro, b_ro);
    ro_scan<<<1, C_ * 32>>>(tau_m_ro, out);
    spkout_kernel<<<dim3(R_, (T_ + 31) / 32), b32>>>(out);
}